// round 6
// baseline (speedup 1.0000x reference)
#include <cuda_runtime.h>

// (4,4,3,192,192) fp32 -> (4,4,2,192,192): per-patch KDE entropies (R=3, h=0.1).
// R6: warp-per-frame (coalesced LDG) + 2-wide horizontal patch coarsening
// (57 shared pair-exps per 2 patches) + SMEM cross-frame exp exchange.

#define WW  192
#define HW  (192 * 192)

#define CM     (-1.9537149f)      // log9 + 1.5*ln(2*pi*0.01)  (C=3 marginal)
#define CJ     (-6.1046541f)      // log9 + 3.0*ln(2*pi*0.01)  (C=6 joint)
#define LN2_9  (0.0770163534f)    // ln(2)/9
#define PSC    (8.4932200f)       // sqrt(50*log2(e)): exp(-50*d2)=ex2(-|p'|^2)

static __device__ __forceinline__ float fast_ex2(float x)
{ float r; asm("ex2.approx.ftz.f32 %0, %1;" : "=f"(r) : "f"(x)); return r; }

static __device__ __forceinline__ float fast_lg2(float x)
{ float r; asm("lg2.approx.f32 %0, %1;" : "=f"(r) : "f"(x)); return r; }

static __device__ __forceinline__ float prod9(const float s[9])
{
    return ((s[0] * s[1]) * (s[2] * s[3])) *
           ((s[4] * s[5]) * (s[6] * s[7])) * s[8];
}

// Border-ring zeroing for one patch's two output channels (cold path).
static __device__ __forceinline__ void zero_border(float* ob, int x, int y)
{
    if (y == 0)   { ob[x + 1] = 0.0f;            ob[HW + x + 1] = 0.0f; }
    if (y == 189) { ob[191*WW + x + 1] = 0.0f;   ob[HW + 191*WW + x + 1] = 0.0f; }
    if (x == 0) {
        ob[(y + 1) * WW] = 0.0f;                 ob[HW + (y + 1) * WW] = 0.0f;
        if (y == 0)   { ob[0] = 0.0f;            ob[HW] = 0.0f; }
        if (y == 189) { ob[191*WW] = 0.0f;       ob[HW + 191*WW] = 0.0f; }
    }
    if (x == 189) {
        ob[(y + 1) * WW + 191] = 0.0f;           ob[HW + (y + 1) * WW + 191] = 0.0f;
        if (y == 0)   { ob[191] = 0.0f;          ob[HW + 191] = 0.0f; }
        if (y == 189) { ob[191*WW + 191] = 0.0f; ob[HW + 191*WW + 191] = 0.0f; }
    }
}

__global__ void __launch_bounds__(128)
je6_kernel(const float* __restrict__ in, float* __restrict__ out)
{
    // Cross-frame exp exchange: warps 1..3 publish their 57 exps.
    __shared__ float sm[3][57][32];

    int lane = threadIdx.x & 31;
    int w    = threadIdx.x >> 5;               // frame handled by this warp
    int x0   = blockIdx.x * 64 + 2 * lane;     // left patch col (thread owns x0, x0+1)
    int y    = blockIdx.y;
    int n    = blockIdx.z;

    bool vT = (x0 < 190);
    bool vB = (x0 + 1 < 190);
    int  xc = vT ? x0 : 188;                   // clamp: keeps loads in-bounds

    // ---- load 3 rows x 4 cols x 3 channels, pre-scaled. Pixel p = r*4+cc ----
    const float* ib = in + ((size_t)(n * 4 + w) * 3) * HW + y * WW + xc;
    float px[12][3];
    #pragma unroll
    for (int c = 0; c < 3; ++c) {
        const float* bc = ib + c * HW;
        #pragma unroll
        for (int r = 0; r < 3; ++r)
            #pragma unroll
            for (int cc = 0; cc < 4; ++cc)
                px[r * 4 + cc][c] = bc[r * WW + cc] * PSC;
    }

    // ---- 57 pair exps (col gap <= 2) + marginal row-sums of both patches ----
    float e[57];
    float sT[9], sB[9];
    #pragma unroll
    for (int i = 0; i < 9; ++i) { sT[i] = 1.0f; sB[i] = 1.0f; }
    {
        int k = 0;
        #pragma unroll
        for (int a = 0; a < 12; ++a) {
            #pragma unroll
            for (int b = a + 1; b < 12; ++b) {
                const int ca = a & 3, cb = b & 3;
                if (((ca > cb) ? (ca - cb) : (cb - ca)) > 2) continue; // pruned
                float d0 = px[a][0] - px[b][0];
                float d1 = px[a][1] - px[b][1];
                float d2 = px[a][2] - px[b][2];
                float nt = -(d0 * d0);
                nt = fmaf(-d1, d1, nt);
                nt = fmaf(-d2, d2, nt);
                float ee = fast_ex2(nt);
                e[k] = ee;
                if (ca <= 2 && cb <= 2) {               // pair inside left patch
                    sT[(a >> 2) * 3 + ca] += ee;
                    sT[(b >> 2) * 3 + cb] += ee;
                }
                if (ca >= 1 && cb >= 1) {               // pair inside right patch
                    sB[(a >> 2) * 3 + ca - 1] += ee;
                    sB[(b >> 2) * 3 + cb - 1] += ee;
                }
                ++k;
            }
        }
    }

    // ---- publish exps of frames 1..3 for the preceding frame's joint ----
    if (w > 0) {
        #pragma unroll
        for (int k = 0; k < 57; ++k) sm[w - 1][k][lane] = e[k];
    }
    __syncthreads();

    // ---- joint entropy: frame w with frame w+1 (w=3: with itself) ----
    float jT[9], jB[9];
    #pragma unroll
    for (int i = 0; i < 9; ++i) { jT[i] = 1.0f; jB[i] = 1.0f; }
    {
        int k = 0;
        #pragma unroll
        for (int a = 0; a < 12; ++a) {
            #pragma unroll
            for (int b = a + 1; b < 12; ++b) {
                const int ca = a & 3, cb = b & 3;
                if (((ca > cb) ? (ca - cb) : (cb - ca)) > 2) continue;
                float en = (w < 3) ? sm[w][k][lane] : e[k];
                float ej = e[k] * en;                   // joint exp = product
                if (ca <= 2 && cb <= 2) {
                    jT[(a >> 2) * 3 + ca] += ej;
                    jT[(b >> 2) * 3 + cb] += ej;
                }
                if (ca >= 1 && cb >= 1) {
                    jB[(a >> 2) * 3 + ca - 1] += ej;
                    jB[(b >> 2) * 3 + cb - 1] += ej;
                }
                ++k;
            }
        }
    }

    // ---- entropies + stores: this thread owns channels 2w, 2w+1 ----
    float* ob = out + ((size_t)(n * 4 + w) * 2) * HW;
    if (vT) {
        int o = (y + 1) * WW + (x0 + 1);
        ob[o]      = CM - LN2_9 * fast_lg2(prod9(sT));
        ob[HW + o] = CJ - LN2_9 * fast_lg2(prod9(jT));
        zero_border(ob, x0, y);
    }
    if (vB) {
        int o = (y + 1) * WW + (x0 + 2);
        ob[o]      = CM - LN2_9 * fast_lg2(prod9(sB));
        ob[HW + o] = CJ - LN2_9 * fast_lg2(prod9(jB));
        zero_border(ob, x0 + 1, y);
    }
}

extern "C" void kernel_launch(void* const* d_in, const int* in_sizes, int n_in,
                              void* d_out, int out_size)
{
    dim3 blk(128, 1, 1);
    dim3 grd(3, 190, 4);   // 3*64 = 192 patch cols (190 valid), 190 rows, 4 batches
    je6_kernel<<<grd, blk>>>((const float*)d_in[0], (float*)d_out);
}

// round 7
// speedup vs baseline: 3.2769x; 3.2769x over previous
#include <cuda_runtime.h>

// (4,4,3,192,192) fp32 -> (4,4,2,192,192): per-patch KDE entropies (R=3, h=0.1).
// R7: lane-split (4 lanes = 4 frames of one patch) with FUSED pair loop:
// shuffle the neighbor frame's exp the moment it is computed (lockstep k),
// accumulate (marginal, joint) in packed f32x2. No persistent e[] array.

#define WW  192
#define HW  (192 * 192)

#define CM     (-1.9537149f)      // log9 + 1.5*ln(2*pi*0.01)  (C=3 marginal)
#define CJ     (-6.1046541f)      // log9 + 3.0*ln(2*pi*0.01)  (C=6 joint)
#define LN2_9  (0.0770163534f)    // ln(2)/9
#define PSC    (8.4932200f)       // sqrt(50*log2(e)): exp(-50*d2)=ex2(-|p'|^2)

#define ONE_ONE 0x3F8000003F800000ULL

typedef unsigned long long u64;

static __device__ __forceinline__ float fast_ex2(float x)
{ float r; asm("ex2.approx.ftz.f32 %0, %1;" : "=f"(r) : "f"(x)); return r; }

static __device__ __forceinline__ float fast_lg2(float x)
{ float r; asm("lg2.approx.f32 %0, %1;" : "=f"(r) : "f"(x)); return r; }

static __device__ __forceinline__ u64 packf2(float lo, float hi)
{ u64 r; asm("mov.b64 %0, {%1, %2};" : "=l"(r) : "f"(lo), "f"(hi)); return r; }

static __device__ __forceinline__ void unpackf2(float& lo, float& hi, u64 v)
{ asm("mov.b64 {%0, %1}, %2;" : "=f"(lo), "=f"(hi) : "l"(v)); }

static __device__ __forceinline__ u64 addf2(u64 a, u64 b)
{ u64 r; asm("add.rn.f32x2 %0, %1, %2;" : "=l"(r) : "l"(a), "l"(b)); return r; }

static __device__ __forceinline__ u64 mulf2(u64 a, u64 b)
{ u64 r; asm("mul.rn.f32x2 %0, %1, %2;" : "=l"(r) : "l"(a), "l"(b)); return r; }

__global__ void __launch_bounds__(128)
je7_kernel(const float* __restrict__ in, float* __restrict__ out)
{
    int lane = threadIdx.x & 31;
    int warp = threadIdx.x >> 5;
    int sf   = lane & 3;          // frame handled by this lane
    int sub  = lane >> 2;         // patch slot within warp (8 patches/warp)

    int x = blockIdx.x * 32 + warp * 8 + sub;   // patch col (valid < 190)
    int y = blockIdx.y;                         // patch row 0..189
    int n = blockIdx.z;

    bool valid = (x < 190);
    int  xc    = valid ? x : 189;   // clamp: edge lanes still shuffle safely

    const float* ib = in + ((size_t)(n * 4 + sf) * 3) * HW + y * WW + xc;

    // ---- load the 3x3 patch x 3 channels of this frame, pre-scaled ----
    float px[9][3];
    #pragma unroll
    for (int c = 0; c < 3; ++c) {
        const float* bc = ib + c * HW;
        #pragma unroll
        for (int dy = 0; dy < 3; ++dy)
            #pragma unroll
            for (int dx = 0; dx < 3; ++dx)
                px[dy * 3 + dx][c] = bc[dy * WW + dx] * PSC;
    }

    // Shuffle source: next frame's lane (same patch); frame 3 pairs with itself.
    int src = (sf == 3) ? lane : (lane + 1);

    // ---- fused pass: 36 exps, immediate shuffle, packed (marg, joint) acc ----
    u64 sp[9];
    #pragma unroll
    for (int i = 0; i < 9; ++i) sp[i] = ONE_ONE;   // diagonal exp(0) for both

    #pragma unroll
    for (int i = 0; i < 9; ++i) {
        #pragma unroll
        for (int j = i + 1; j < 9; ++j) {
            float d0 = px[i][0] - px[j][0];
            float d1 = px[i][1] - px[j][1];
            float d2 = px[i][2] - px[j][2];
            float nt = -(d0 * d0);
            nt = fmaf(-d1, d1, nt);
            nt = fmaf(-d2, d2, nt);
            float ee = fast_ex2(nt);
            float en = __shfl_sync(0xffffffffu, ee, src);  // lockstep: same pair k
            float ej = ee * en;                            // joint exp = product
            u64 ad = packf2(ee, ej);
            sp[i] = addf2(sp[i], ad);
            sp[j] = addf2(sp[j], ad);
        }
    }

    // ---- packed product over the 9 row-sums, then two logs ----
    u64 pr = mulf2(mulf2(mulf2(sp[0], sp[1]), mulf2(sp[2], sp[3])),
                   mulf2(mulf2(sp[4], sp[5]), mulf2(sp[6], sp[7])));
    pr = mulf2(pr, sp[8]);
    float pm, pj;
    unpackf2(pm, pj, pr);
    float hm = CM - LN2_9 * fast_lg2(pm);
    float hj = CJ - LN2_9 * fast_lg2(pj);

    // ---- stores: this thread owns channels 2*sf, 2*sf+1 of batch n ----
    if (valid) {
        float* ob = out + ((size_t)(n * 4 + sf) * 2) * HW;
        int oofs = (y + 1) * WW + (x + 1);
        ob[oofs]      = hm;
        ob[HW + oofs] = hj;

        // border ring zeroing (output is poisoned 0xAA)
        if (y == 0)   { ob[x + 1] = 0.0f;            ob[HW + x + 1] = 0.0f; }
        if (y == 189) { ob[191*WW + x + 1] = 0.0f;   ob[HW + 191*WW + x + 1] = 0.0f; }
        if (x == 0) {
            ob[(y + 1) * WW] = 0.0f;      ob[HW + (y + 1) * WW] = 0.0f;
            if (y == 0)   { ob[0] = 0.0f;            ob[HW] = 0.0f; }
            if (y == 189) { ob[191*WW] = 0.0f;       ob[HW + 191*WW] = 0.0f; }
        }
        if (x == 189) {
            ob[(y + 1) * WW + 191] = 0.0f; ob[HW + (y + 1) * WW + 191] = 0.0f;
            if (y == 0)   { ob[191] = 0.0f;          ob[HW + 191] = 0.0f; }
            if (y == 189) { ob[191*WW + 191] = 0.0f; ob[HW + 191*WW + 191] = 0.0f; }
        }
    }
}

extern "C" void kernel_launch(void* const* d_in, const int* in_sizes, int n_in,
                              void* d_out, int out_size)
{
    dim3 blk(128, 1, 1);
    dim3 grd(6, 190, 4);   // 6 * 4 warps * 8 patches = 192 cols; 190 rows; 4 batches
    je7_kernel<<<grd, blk>>>((const float*)d_in[0], (float*)d_out);
}